// round 2
// baseline (speedup 1.0000x reference)
#include <cuda_runtime.h>

// LBFGS two-loop recursion, M=32 back + 32 fwd scans.
// One CTA per batch (64 CTAs) x 512 threads; 16 floats (4 float4) per thread
// per row. q + current s,y + prefetched next s,y all register-resident
// (~80 regs of state; 512 thr/CTA -> 128-reg budget, no spills).
// Per-step reduction: warp shfl -> 16 partials -> ONE __syncthreads ->
// broadcast LDS sum. Parity double-buffer on the partials removes the
// second barrier (WAR protection).

#define MM 32
#define BB 64
#define DD 8192
#define NT 512
#define K4 4                    // float4 per row per thread
#define F4ROW (DD / 4)          // 2048
#define ROWSTRIDE ((size_t)BB * F4ROW)   // float4 stride between history rows

__device__ __forceinline__ float dot4(float4 a, float4 b) {
    return a.x * b.x + a.y * b.y + a.z * b.z + a.w * b.w;
}

// Reduce N per-thread values across the block. One __syncthreads.
// red must point at a 16*N float region unique to this step (parity buffer).
template <int N>
__device__ __forceinline__ void block_reduce(float* v, float* red) {
    const int lane = threadIdx.x & 31;
    const int wid  = threadIdx.x >> 5;
#pragma unroll
    for (int off = 16; off > 0; off >>= 1) {
#pragma unroll
        for (int n = 0; n < N; ++n)
            v[n] += __shfl_xor_sync(0xffffffffu, v[n], off);
    }
    if (lane == 0) {
#pragma unroll
        for (int n = 0; n < N; ++n) red[n * 16 + wid] = v[n];
    }
    __syncthreads();
#pragma unroll
    for (int n = 0; n < N; ++n) {
        const float4* r4 = (const float4*)(red + n * 16);
        float4 p0 = r4[0], p1 = r4[1], p2 = r4[2], p3 = r4[3];
        v[n] = (p0.x + p0.y + p0.z + p0.w) + (p1.x + p1.y + p1.z + p1.w) +
               (p2.x + p2.y + p2.z + p2.w) + (p3.x + p3.y + p3.z + p3.w);
    }
}

__global__ __launch_bounds__(NT, 1)
void lbfgs_scan_kernel(const float* __restrict__ S,
                       const float* __restrict__ Y,
                       const float* __restrict__ FRC,
                       float* __restrict__ OUT) {
    const int b   = blockIdx.x;
    const int tid = threadIdx.x;

    __shared__ float red[2][48];     // parity double-buffered partials (3 x 16)
    __shared__ float r_arr[MM];
    __shared__ float a_arr[MM];

    const float4* S4 = (const float4*)S;
    const float4* Y4 = (const float4*)Y;

    // q = -frc
    float4 q[K4];
    {
        const float4* F4 = (const float4*)FRC + (size_t)b * F4ROW + tid;
#pragma unroll
        for (int k = 0; k < K4; ++k) {
            float4 t = F4[k * NT];
            q[k].x = -t.x; q[k].y = -t.y; q[k].z = -t.z; q[k].w = -t.w;
        }
    }

    const size_t tbase = (size_t)b * F4ROW + tid;   // row-i base: tbase + i*ROWSTRIDE

    float4 sc[K4], yc[K4], sn[K4], yn[K4];
    {
        const size_t rb = tbase + (size_t)(MM - 1) * ROWSTRIDE;
#pragma unroll
        for (int k = 0; k < K4; ++k) { sc[k] = S4[rb + k * NT]; yc[k] = Y4[rb + k * NT]; }
    }

    float gscale = 1.0f;

    // ---------------- backward: i = M-1 .. 0 ----------------
#pragma unroll 1
    for (int step = 0; step < MM; ++step) {
        const int i     = MM - 1 - step;
        const int inext = (i > 0) ? (i - 1) : 0;     // i==0 preloads row 0 for fwd

        const size_t nb = tbase + (size_t)inext * ROWSTRIDE;
#pragma unroll
        for (int k = 0; k < K4; ++k) { sn[k] = S4[nb + k * NT]; yn[k] = Y4[nb + k * NT]; }

        float v[3];
        v[0] = 0.0f; v[1] = 0.0f; v[2] = 0.0f;
#pragma unroll
        for (int k = 0; k < K4; ++k) {
            v[0] += dot4(sc[k], yc[k]);
            v[1] += dot4(sc[k], q[k]);
        }
        if (step == 0) {
#pragma unroll
            for (int k = 0; k < K4; ++k) v[2] += dot4(yc[k], yc[k]);
        }

        block_reduce<3>(v, red[step & 1]);

        const float r = 1.0f / v[0];
        const float a = r * v[1];
        if (tid == 0) { r_arr[i] = r; a_arr[i] = a; }
        if (step == 0) gscale = v[0] / v[2];

#pragma unroll
        for (int k = 0; k < K4; ++k) {
            q[k].x -= a * yc[k].x; q[k].y -= a * yc[k].y;
            q[k].z -= a * yc[k].z; q[k].w -= a * yc[k].w;
        }
#pragma unroll
        for (int k = 0; k < K4; ++k) { sc[k] = sn[k]; yc[k] = yn[k]; }
    }

#pragma unroll
    for (int k = 0; k < K4; ++k) {
        q[k].x *= gscale; q[k].y *= gscale; q[k].z *= gscale; q[k].w *= gscale;
    }

    // ---------------- forward: i = 0 .. M-1 (cur rows = i=0) ----------------
#pragma unroll 1
    for (int i = 0; i < MM; ++i) {
        const int inext = (i < MM - 1) ? (i + 1) : (MM - 1);
        const size_t nb = tbase + (size_t)inext * ROWSTRIDE;
#pragma unroll
        for (int k = 0; k < K4; ++k) { sn[k] = S4[nb + k * NT]; yn[k] = Y4[nb + k * NT]; }

        float v[1];
        v[0] = 0.0f;
#pragma unroll
        for (int k = 0; k < K4; ++k) v[0] += dot4(yc[k], q[k]);

        block_reduce<1>(v, red[i & 1]);

        // r_arr/a_arr writes (backward, pre-barrier) are visible: the reduce's
        // __syncthreads orders them before these reads.
        const float bi = r_arr[i] * v[0];
        const float ci = a_arr[i] - bi;

#pragma unroll
        for (int k = 0; k < K4; ++k) {
            q[k].x += ci * sc[k].x; q[k].y += ci * sc[k].y;
            q[k].z += ci * sc[k].z; q[k].w += ci * sc[k].w;
        }
#pragma unroll
        for (int k = 0; k < K4; ++k) { sc[k] = sn[k]; yc[k] = yn[k]; }
    }

    // out = -q
    float4* O4 = (float4*)OUT + (size_t)b * F4ROW + tid;
#pragma unroll
    for (int k = 0; k < K4; ++k) {
        float4 o;
        o.x = -q[k].x; o.y = -q[k].y; o.z = -q[k].z; o.w = -q[k].w;
        O4[k * NT] = o;
    }
}

extern "C" void kernel_launch(void* const* d_in, const int* in_sizes, int n_in,
                              void* d_out, int out_size) {
    const float* S   = (const float*)d_in[0];  // (M, B, D) fp32
    const float* Y   = (const float*)d_in[1];  // (M, B, D) fp32
    const float* FRC = (const float*)d_in[2];  // (B, D)    fp32
    float* OUT = (float*)d_out;                // (B, D)    fp32

    lbfgs_scan_kernel<<<BB, NT>>>(S, Y, FRC, OUT);
}

// round 3
// speedup vs baseline: 1.4322x; 1.4322x over previous
#include <cuda_runtime.h>
#include <cstdint>

// LBFGS two-loop recursion (M=32 back + 32 fwd).
// One CTA per batch (64 CTAs) x 1024 threads.
// s/y rows stream through a 3-stage SMEM ring via cp.async.bulk (TMA bulk) +
// mbarrier — zero registers, zero issue slots spent on the stream. Only the
// carry q (8 floats/thread) is register-resident, so 1024 threads fit in the
// 64-reg budget with no spills. Per-CTA in-flight bytes = 192KB (3 stages),
// fully hiding DRAM latency; step time bounded by SMEM crossbar + reduce.

#define MM 32
#define BB 64
#define DD 8192
#define NT 1024
#define F4ROW (DD / 4)
#define STAGES 3
#define ROW_BYTES (DD * 4)               // 32 KB per row
#define STAGE_BYTES (2 * ROW_BYTES)      // s + y
#define SMEM_SMALL 1024
#define SMEM_TOTAL (SMEM_SMALL + STAGES * STAGE_BYTES)   // 197632 B

// small-region layout (offsets into smem):
//   0   : mbar[3] (8B each)
//   128 : red[3*32] warp partials
//   640 : fin[4]
//   704 : r_arr[32]
//   832 : a_arr[32]

__device__ __forceinline__ uint32_t smem_u32(const void* p) {
    return (uint32_t)__cvta_generic_to_shared(p);
}

__device__ __forceinline__ void mbar_init(uint32_t mbar, uint32_t count) {
    asm volatile("mbarrier.init.shared::cta.b64 [%0], %1;" :: "r"(mbar), "r"(count));
}

__device__ __forceinline__ void mbar_expect_tx(uint32_t mbar, uint32_t bytes) {
    asm volatile("mbarrier.arrive.expect_tx.shared::cta.b64 _, [%0], %1;"
                 :: "r"(mbar), "r"(bytes) : "memory");
}

__device__ __forceinline__ void bulk_g2s(uint32_t dst, const void* src,
                                         uint32_t bytes, uint32_t mbar) {
    asm volatile(
        "cp.async.bulk.shared::cluster.global.mbarrier::complete_tx::bytes "
        "[%0], [%1], %2, [%3];"
        :: "r"(dst), "l"(src), "r"(bytes), "r"(mbar) : "memory");
}

__device__ __forceinline__ void mbar_wait(uint32_t mbar, uint32_t parity) {
    uint32_t done;
    asm volatile(
        "{\n\t.reg .pred p;\n\t"
        "mbarrier.try_wait.parity.acquire.cta.shared::cta.b64 p, [%1], %2;\n\t"
        "selp.b32 %0, 1, 0, p;\n\t}"
        : "=r"(done) : "r"(mbar), "r"(parity) : "memory");
    if (!done) {
        asm volatile(
            "{\n\t.reg .pred P1;\n\t"
            "WL_%=:\n\t"
            "mbarrier.try_wait.parity.acquire.cta.shared::cta.b64 P1, [%0], %1, 0x989680;\n\t"
            "@P1 bra.uni WD_%=;\n\t"
            "bra.uni WL_%=;\n\t"
            "WD_%=:\n\t}"
            :: "r"(mbar), "r"(parity) : "memory");
    }
}

__device__ __forceinline__ float dot4(float4 a, float4 b) {
    return a.x * b.x + a.y * b.y + a.z * b.z + a.w * b.w;
}

// block reduce of N values across 32 warps; two __syncthreads; result in v[n]
// for every thread (broadcast via fin).
template <int N>
__device__ __forceinline__ void block_reduce(float* v, float* red, float* fin) {
    const int lane = threadIdx.x & 31;
    const int wid  = threadIdx.x >> 5;
#pragma unroll
    for (int off = 16; off > 0; off >>= 1)
#pragma unroll
        for (int n = 0; n < N; ++n)
            v[n] += __shfl_xor_sync(0xffffffffu, v[n], off);
    if (lane == 0)
#pragma unroll
        for (int n = 0; n < N; ++n) red[n * 32 + wid] = v[n];
    __syncthreads();
    if (wid == 0) {
#pragma unroll
        for (int n = 0; n < N; ++n) {
            float x = red[n * 32 + lane];
#pragma unroll
            for (int off = 16; off > 0; off >>= 1)
                x += __shfl_xor_sync(0xffffffffu, x, off);
            if (lane == 0) fin[n] = x;
        }
    }
    __syncthreads();
#pragma unroll
    for (int n = 0; n < N; ++n) v[n] = fin[n];
}

__device__ __forceinline__ int seq_row(int t) {           // palindromic order
    return (t < MM) ? (MM - 1 - t) : (t - MM);
}

__global__ __launch_bounds__(NT, 1)
void lbfgs_tma_kernel(const float* __restrict__ S,
                      const float* __restrict__ Y,
                      const float* __restrict__ FRC,
                      float* __restrict__ OUT) {
    extern __shared__ __align__(1024) char smem[];
    float* red   = (float*)(smem + 128);
    float* fin   = (float*)(smem + 640);
    float* r_arr = (float*)(smem + 704);
    float* a_arr = (float*)(smem + 832);
    const uint32_t mbar0  = smem_u32(smem);
    const uint32_t stage0 = smem_u32(smem + SMEM_SMALL);

    const int b   = blockIdx.x;
    const int tid = threadIdx.x;

    if (tid == 0) {
#pragma unroll
        for (int s = 0; s < STAGES; ++s) mbar_init(mbar0 + s * 8, 1);
    }
    asm volatile("fence.proxy.async.shared::cta;" ::: "memory");
    __syncthreads();

    auto issue = [&](int stage, int t) {
        const int row = seq_row(t);
        const size_t off = ((size_t)row * BB + b) * DD;
        const uint32_t mbar = mbar0 + stage * 8;
        const uint32_t dst  = stage0 + stage * STAGE_BYTES;
        mbar_expect_tx(mbar, STAGE_BYTES);
        bulk_g2s(dst,             S + off, ROW_BYTES, mbar);
        bulk_g2s(dst + ROW_BYTES, Y + off, ROW_BYTES, mbar);
    };

    if (tid == 0) {
        issue(0, 0);
        issue(1, 1);
        issue(2, 2);
    }

    // q = -frc (register-resident)
    float4 q0, q1;
    {
        const float4* F4 = (const float4*)FRC + (size_t)b * F4ROW;
        float4 a = F4[tid], c = F4[tid + NT];
        q0.x = -a.x; q0.y = -a.y; q0.z = -a.z; q0.w = -a.w;
        q1.x = -c.x; q1.y = -c.y; q1.z = -c.z; q1.w = -c.w;
    }

    float gscale = 1.0f;

#pragma unroll 1
    for (int t = 0; t < 2 * MM; ++t) {
        const int stage = t % STAGES;
        const uint32_t parity = (uint32_t)(t / STAGES) & 1u;
        const uint32_t mbar = mbar0 + stage * 8;

        if (t == MM) {  // between passes: q *= g
            q0.x *= gscale; q0.y *= gscale; q0.z *= gscale; q0.w *= gscale;
            q1.x *= gscale; q1.y *= gscale; q1.z *= gscale; q1.w *= gscale;
        }

        mbar_wait(mbar, parity);

        const float4* sS = (const float4*)(smem + SMEM_SMALL + stage * STAGE_BYTES);
        const float4* sY = (const float4*)(smem + SMEM_SMALL + stage * STAGE_BYTES + ROW_BYTES);
        float4 s0 = sS[tid], s1 = sS[tid + NT];
        float4 y0 = sY[tid], y1 = sY[tid + NT];

        if (t < MM) {
            // -------- backward step, i = MM-1-t --------
            float v[3];
            v[0] = dot4(s0, y0) + dot4(s1, y1);
            v[1] = dot4(s0, q0) + dot4(s1, q1);
            v[2] = (t == 0) ? (dot4(y0, y0) + dot4(y1, y1)) : 0.0f;
            block_reduce<3>(v, red, fin);

            const float r = 1.0f / v[0];
            const float a = r * v[1];
            const int   i = MM - 1 - t;
            if (tid == 0) { r_arr[i] = r; a_arr[i] = a; }
            if (t == 0) gscale = v[0] / v[2];

            q0.x -= a * y0.x; q0.y -= a * y0.y; q0.z -= a * y0.z; q0.w -= a * y0.w;
            q1.x -= a * y1.x; q1.y -= a * y1.y; q1.z -= a * y1.z; q1.w -= a * y1.w;
        } else {
            // -------- forward step, i = t-MM --------
            float v[1];
            v[0] = dot4(y0, q0) + dot4(y1, q1);
            block_reduce<1>(v, red, fin);

            const int   i = t - MM;
            const float c = a_arr[i] - r_arr[i] * v[0];

            q0.x += c * s0.x; q0.y += c * s0.y; q0.z += c * s0.z; q0.w += c * s0.w;
            q1.x += c * s1.x; q1.y += c * s1.y; q1.z += c * s1.z; q1.w += c * s1.w;
        }

        // stage fully consumed (all LDS happened before the reduce's barriers)
        if (tid == 0 && t + STAGES < 2 * MM) issue(stage, t + STAGES);
    }

    // out = -q
    float4* O4 = (float4*)OUT + (size_t)b * F4ROW;
    float4 o0, o1;
    o0.x = -q0.x; o0.y = -q0.y; o0.z = -q0.z; o0.w = -q0.w;
    o1.x = -q1.x; o1.y = -q1.y; o1.z = -q1.z; o1.w = -q1.w;
    O4[tid]      = o0;
    O4[tid + NT] = o1;
}

extern "C" void kernel_launch(void* const* d_in, const int* in_sizes, int n_in,
                              void* d_out, int out_size) {
    const float* S   = (const float*)d_in[0];  // (M, B, D) fp32
    const float* Y   = (const float*)d_in[1];  // (M, B, D) fp32
    const float* FRC = (const float*)d_in[2];  // (B, D)    fp32
    float* OUT = (float*)d_out;                // (B, D)    fp32

    static bool attr_set = false;
    if (!attr_set) {
        cudaFuncSetAttribute(lbfgs_tma_kernel,
                             cudaFuncAttributeMaxDynamicSharedMemorySize,
                             SMEM_TOTAL);
        attr_set = true;
    }
    lbfgs_tma_kernel<<<BB, NT, SMEM_TOTAL>>>(S, Y, FRC, OUT);
}